// round 15
// baseline (speedup 1.0000x reference)
#include <cuda_runtime.h>
#include <cstdint>

#define NHEADS 16
#define OD     1024
#define OF     768        // fp32-exact options [0,768)
#define OI     256        // int8 options [768,1024)
#define KD     128
#define NK4    32
#define NTOK   4096
#define EDIM   2048
#define TM     64         // tokens per main block
#define NTHR   256
#define CWF    64         // fp32 options per iter
#define CWQ    32         // int8 options per iter (iters 0-7 only)
#define NIT    12
#define TH     0.032f
#define NEG_INF (-3.402823466e38f)
#define R2CAP  1024

typedef unsigned long long u64;

// ---------------- device scratch ----------------
__device__ __align__(16) float g_wt[(size_t)NHEADS*KD*OD];   // [h][k][o] fp32 transposed (ALL)
__device__ __align__(16) int   g_wq[(size_t)NHEADS*NK4*OI];  // [h][k4][o-768] packed int8
__device__ __align__(16) float g_sw[NHEADS*OI];
__device__ int      g_idx[NTOK*NHEADS];
__device__ unsigned g_r1n;
__device__ uint2    g_r1[NTOK*NHEADS];
__device__ unsigned g_r2n[NHEADS];
__device__ int      g_r2[NHEADS][R2CAP];
__device__ u64      g_best[NTOK*NHEADS];

// ---------------- main-kernel smem (bytes), double-buffered W ----------------
// Staging [64][132] f32 = 33792B aliases the WF double buffer (2x32768).
// Safe: all W cp.async groups are issued AFTER the prologue's final
// __syncthreads() (staging fully consumed by then).
#define SM_XS2 0                        // u64 [128 k][64 tok] x dup    (65536)
#define SM_WF  65536                    // 2 x u64 [128 k][32 pairs]    (65536)
#define SM_STG SM_WF                    // f32 [64 tok][132] staging (alias)
#define SM_WQ  131072                   // 2 x int [32 k4][32 opt]      (8192)
#define SM_XQ  139264                   // int [32 k4][64 tok]          (8192)
#define SM_SWS 147456                   // 2 x 32 f32                   (256)
#define SM_SXS 147712                   // 64 f32
#define SM_INV 147968                   // 64 f32
#define SM_TOT 148224

// ---------------- helpers ----------------
#define CP16(dst, src) \
    asm volatile("cp.async.cg.shared.global [%0], [%1], 16;" :: "r"(dst), "l"(src))
#define CPCOMMIT() asm volatile("cp.async.commit_group;" ::: "memory")
#define CPWAIT1()  asm volatile("cp.async.wait_group 1;" ::: "memory")
#define CPWAIT0()  asm volatile("cp.async.wait_group 0;" ::: "memory")

__device__ __forceinline__ uint32_t smem_u32(const void* p) {
    uint32_t a;
    asm("{ .reg .u64 t; cvta.to.shared.u64 t, %1; cvt.u32.u64 %0, t; }" : "=r"(a) : "l"(p));
    return a;
}
__device__ __forceinline__ u64 pack2(float lo, float hi) {
    u64 r; asm("mov.b64 %0, {%1, %2};" : "=l"(r) : "f"(lo), "f"(hi)); return r;
}
__device__ __forceinline__ void unpack2(u64 v, float &lo, float &hi) {
    asm("mov.b64 {%0, %1}, %2;" : "=f"(lo), "=f"(hi) : "l"(v));
}
__device__ __forceinline__ u64 ffma2(u64 a, u64 b, u64 c) {
    u64 d; asm("fma.rn.f32x2 %0, %1, %2, %3;" : "=l"(d) : "l"(a), "l"(b), "l"(c));
    return d;
}
__device__ __forceinline__ int q8(float v, float inv) {
    int a = __float2int_rn(v * inv);
    return a < -127 ? -127 : (a > 127 ? 127 : a);
}
__device__ __forceinline__ void merge3(float& a1, float& a2, float& a3, int& j1, int& j2,
                                       float b1, float b2, float b3, int k1, int k2) {
    if (b1 > a1 || (b1 == a1 && k1 < j1)) {
        float t1 = a1, t2 = a2, t3 = a3; int u1 = j1, u2 = j2;
        a1 = b1; a2 = b2; a3 = b3; j1 = k1; j2 = k2;
        b1 = t1; b2 = t2; b3 = t3; k1 = u1; k2 = u2;
    }
    if (b1 > a2 || (b1 == a2 && k1 < j2)) { a3 = fmaxf(a2, b2); a2 = b1; j2 = k1; }
    else                                  { a3 = fmaxf(a3, b1); }
}
__device__ __forceinline__ unsigned enc_f(float f) {
    unsigned u = __float_as_uint(f);
    return (u & 0x80000000u) ? ~u : (u | 0x80000000u);
}

// ---------------- w preprocessing ----------------
__global__ __launch_bounds__(256) void prep_w_kernel(const float* __restrict__ w) {
    __shared__ float trf[128 * 33];
    __shared__ float sws_s[32], invs[32];
    if (blockIdx.x == 0 && blockIdx.y == 0) {
        if (threadIdx.x == 0) g_r1n = 0;
        if (threadIdx.x < NHEADS) g_r2n[threadIdx.x] = 0;
    }
    const int h = blockIdx.y, o0 = blockIdx.x * 32;
    const int tid = threadIdx.x, l = tid & 31, wid = tid >> 5;

    for (int r = wid; r < 32; r += 8) {
        float4 v = *(const float4*)(w + ((size_t)h * OD + o0 + r) * KD + l * 4);
        trf[(4*l+0)*33 + r] = v.x; trf[(4*l+1)*33 + r] = v.y;
        trf[(4*l+2)*33 + r] = v.z; trf[(4*l+3)*33 + r] = v.w;
        if (o0 >= OF) {
            float mx = fmaxf(fmaxf(fabsf(v.x), fabsf(v.y)), fmaxf(fabsf(v.z), fabsf(v.w)));
#pragma unroll
            for (int off = 16; off; off >>= 1)
                mx = fmaxf(mx, __shfl_xor_sync(0xffffffffu, mx, off));
            if (l == 0) {
                sws_s[r] = mx * (1.f / 127.f);
                invs[r]  = (mx > 0.f) ? 127.f / mx : 0.f;
            }
        }
    }
    __syncthreads();
    for (int i = tid; i < 4096; i += 256) {
        int k = i >> 5, rl = i & 31;
        g_wt[((size_t)h * KD + k) * OD + o0 + rl] = trf[k * 33 + rl];
    }
    if (o0 >= OF) {
        for (int i = tid; i < 1024; i += 256) {
            int k4 = i >> 5, rl = i & 31;
            float inv = invs[rl];
            int a0 = q8(trf[(4*k4+0)*33 + rl], inv);
            int a1 = q8(trf[(4*k4+1)*33 + rl], inv);
            int a2 = q8(trf[(4*k4+2)*33 + rl], inv);
            int a3 = q8(trf[(4*k4+3)*33 + rl], inv);
            g_wq[((size_t)h * NK4 + k4) * OI + (o0 - OF) + rl] =
                (a0 & 255) | ((a1 & 255) << 8) | ((a2 & 255) << 16) | ((a3 & 255) << 24);
        }
        if (tid < 32) g_sw[h * OI + (o0 - OF) + tid] = sws_s[tid];
    }
}

// issue one iteration's W loads into buffer buf (one commit group)
__device__ __forceinline__ void issue_w(uint32_t sb, const float* wtsrc, const int* wqsrc,
                                        const float* swsrc, int it, int buf, int tid) {
#pragma unroll
    for (int r = 0; r < 8; r++) {
        int i = tid + NTHR * r;
        int k = i >> 4, v = i & 15;
        CP16(sb + SM_WF + buf * 32768 + k * 256 + v * 16,
             wtsrc + (size_t)k * OD + it * CWF + v * 4);
    }
    if (it < 8) {
        int k4 = tid >> 3, s = tid & 7;
        CP16(sb + SM_WQ + buf * 4096 + k4 * 128 + s * 16,
             wqsrc + (size_t)k4 * OI + it * CWQ + s * 4);
        if (tid < 8)
            CP16(sb + SM_SWS + buf * 128 + tid * 16, swsrc + it * CWQ + tid * 4);
    }
    CPCOMMIT();
}

// ---------------- main hybrid kernel: 64 tok x 1 head, 256 threads ----------------
// 16 tx x 16 ty; thread tile = 4 tokens x (4 fp32 + 2 int8) options per iter.
// W double-buffered via cp.async groups (R5 pattern): loads for it+1 always in flight.
__global__ __launch_bounds__(NTHR, 1) void vq_hybrid_kernel(const float* __restrict__ x) {
    extern __shared__ char sm[];
    const uint32_t sb = smem_u32(sm);
    const int tid = threadIdx.x, l = tid & 31, wrp = tid >> 5;
    const int tx = tid & 15, ty = tid >> 4;
    const int t0 = blockIdx.x * TM, h = blockIdx.y;

    const float* wtsrc = g_wt + (size_t)h * KD * OD;
    const int*   wqsrc = g_wq + (size_t)h * NK4 * OI;
    const float* swsrc = g_sw + (size_t)h * OI;

    // ---- prologue: 64 tokens, staged once (staging aliases WF buffers) ----
    {
        float* stg = (float*)(sm + SM_STG);        // [64][132], 16B-aligned rows
        float* sxs = (float*)(sm + SM_SXS);
        float* inv = (float*)(sm + SM_INV);
        u64*   xs2 = (u64*)(sm + SM_XS2);
        int*   xq  = (int*)(sm + SM_XQ);
#pragma unroll
        for (int rr = 0; rr < 8; rr++) {
            int tl = wrp * 8 + rr;                 // 0..63
            float4 v = *(const float4*)(x + (size_t)(t0 + tl) * EDIM + h * KD + l * 4);
            float mx = fmaxf(fmaxf(fabsf(v.x), fabsf(v.y)), fmaxf(fabsf(v.z), fabsf(v.w)));
#pragma unroll
            for (int off = 16; off; off >>= 1)
                mx = fmaxf(mx, __shfl_xor_sync(0xffffffffu, mx, off));
            if (l == 0) {
                sxs[tl] = mx * (1.f / 127.f);
                inv[tl] = (mx > 0.f) ? 127.f / mx : 0.f;
            }
            *(float4*)&stg[tl * 132 + l * 4] = v;
        }
        __syncthreads();
        {
            const int t = tid & 63;                // local token
            const float invv = inv[t];
#pragma unroll
            for (int r = 0; r < 8; r++) {
                int k4 = (tid >> 6) + 4 * r;       // 0..31
                float4 f = *(const float4*)&stg[t * 132 + 4 * k4];
                xs2[(4*k4+0) * TM + t] = pack2(f.x, f.x);
                xs2[(4*k4+1) * TM + t] = pack2(f.y, f.y);
                xs2[(4*k4+2) * TM + t] = pack2(f.z, f.z);
                xs2[(4*k4+3) * TM + t] = pack2(f.w, f.w);
                int a0 = q8(f.x, invv), a1 = q8(f.y, invv);
                int a2 = q8(f.z, invv), a3 = q8(f.w, invv);
                xq[k4 * TM + t] =
                    (a0 & 255) | ((a1 & 255) << 8) | ((a2 & 255) << 16) | ((a3 & 255) << 24);
            }
        }
        __syncthreads();   // staging fully consumed -> WF buffers free
    }

    // ---- pipeline prologue: issue W for it=0 and it=1 ----
    issue_w(sb, wtsrc, wqsrc, swsrc, 0, 0, tid);
    issue_w(sb, wtsrc, wqsrc, swsrc, 1, 1, tid);

    float fv[4]; int fi[4];
    float v1[4], v2[4], v3[4]; int i1[4], i2[4];
#pragma unroll
    for (int p = 0; p < 4; p++) {
        fv[p] = NEG_INF; fi[p] = 0;
        v1[p] = v2[p] = v3[p] = NEG_INF; i1[p] = OF; i2[p] = OF;
    }

#pragma unroll 1
    for (int it = 0; it < NIT; it++) {
        const int buf = it & 1;
        if (it < NIT - 1) { CPWAIT1(); } else { CPWAIT0(); }
        __syncthreads();   // buf[it&1] ready for all threads

        u64 facc[4][2];
        int iacc[4][2];
#pragma unroll
        for (int p = 0; p < 4; p++) {
            facc[p][0] = facc[p][1] = 0ULL;
            iacc[p][0] = iacc[p][1] = 0;
        }

        // generic-pointer bases for smem dereference (sm is char*; sb only for cp.async)
        const char* wfb = sm + SM_WF + buf * 32768;
        if (it < 8) {
            const char* wqb = sm + SM_WQ + buf * 4096;
#pragma unroll 2
            for (int k4 = 0; k4 < NK4; k4++) {
                int4 xqv = *(const int4*)(sm + SM_XQ + (k4 * TM + ty * 4) * 4);
                int2 wqv = *(const int2*)(wqb + (k4 * 32 + tx * 2) * 4);
                iacc[0][0] = __dp4a(xqv.x, wqv.x, iacc[0][0]);
                iacc[0][1] = __dp4a(xqv.x, wqv.y, iacc[0][1]);
                iacc[1][0] = __dp4a(xqv.y, wqv.x, iacc[1][0]);
                iacc[1][1] = __dp4a(xqv.y, wqv.y, iacc[1][1]);
                iacc[2][0] = __dp4a(xqv.z, wqv.x, iacc[2][0]);
                iacc[2][1] = __dp4a(xqv.z, wqv.y, iacc[2][1]);
                iacc[3][0] = __dp4a(xqv.w, wqv.x, iacc[3][0]);
                iacc[3][1] = __dp4a(xqv.w, wqv.y, iacc[3][1]);
#pragma unroll
                for (int j = 0; j < 4; j++) {
                    const int k = k4 * 4 + j;
                    ulonglong2 xa = *(const ulonglong2*)(sm + SM_XS2 + (k * TM + ty * 4) * 8);
                    ulonglong2 xb = *(const ulonglong2*)(sm + SM_XS2 + (k * TM + ty * 4 + 2) * 8);
                    ulonglong2 wp = *(const ulonglong2*)(wfb + (k * 32 + tx * 2) * 8);
                    facc[0][0] = ffma2(xa.x, wp.x, facc[0][0]);
                    facc[0][1] = ffma2(xa.x, wp.y, facc[0][1]);
                    facc[1][0] = ffma2(xa.y, wp.x, facc[1][0]);
                    facc[1][1] = ffma2(xa.y, wp.y, facc[1][1]);
                    facc[2][0] = ffma2(xb.x, wp.x, facc[2][0]);
                    facc[2][1] = ffma2(xb.x, wp.y, facc[2][1]);
                    facc[3][0] = ffma2(xb.y, wp.x, facc[3][0]);
                    facc[3][1] = ffma2(xb.y, wp.y, facc[3][1]);
                }
            }
        } else {
#pragma unroll 2
            for (int k4 = 0; k4 < NK4; k4++) {
#pragma unroll
                for (int j = 0; j < 4; j++) {
                    const int k = k4 * 4 + j;
                    ulonglong2 xa = *(const ulonglong2*)(sm + SM_XS2 + (k * TM + ty * 4) * 8);
                    ulonglong2 xb = *(const ulonglong2*)(sm + SM_XS2 + (k * TM + ty * 4 + 2) * 8);
                    ulonglong2 wp = *(const ulonglong2*)(wfb + (k * 32 + tx * 2) * 8);
                    facc[0][0] = ffma2(xa.x, wp.x, facc[0][0]);
                    facc[0][1] = ffma2(xa.x, wp.y, facc[0][1]);
                    facc[1][0] = ffma2(xa.y, wp.x, facc[1][0]);
                    facc[1][1] = ffma2(xa.y, wp.y, facc[1][1]);
                    facc[2][0] = ffma2(xb.x, wp.x, facc[2][0]);
                    facc[2][1] = ffma2(xb.x, wp.y, facc[2][1]);
                    facc[3][0] = ffma2(xb.y, wp.x, facc[3][0]);
                    facc[3][1] = ffma2(xb.y, wp.y, facc[3][1]);
                }
            }
        }

        // fold fp32 (exact top-1; thread owns options it*64 + tx*4 .. +3, ascending)
#pragma unroll
        for (int p = 0; p < 4; p++) {
#pragma unroll
            for (int j = 0; j < 2; j++) {
                const int o = it * CWF + tx * 4 + j * 2;
                float q0, q1; unpack2(facc[p][j], q0, q1);
                if (q0 > fv[p]) { fv[p] = q0; fi[p] = o; }
                if (q1 > fv[p]) { fv[p] = q1; fi[p] = o + 1; }
            }
        }
        // fold int8 (top-3)
        if (it < 8) {
            float2 s2 = *(const float2*)(sm + SM_SWS + buf * 128 + tx * 8);
            const int ob = OF + it * CWQ + tx * 2;
#pragma unroll
            for (int p = 0; p < 4; p++) {
#pragma unroll
                for (int u = 0; u < 2; u++) {
                    float v = (float)iacc[p][u] * (u ? s2.y : s2.x);
                    int o = ob + u;
                    if (v > v1[p]) { v3[p] = v2[p]; v2[p] = v1[p]; i2[p] = i1[p]; v1[p] = v; i1[p] = o; }
                    else if (v > v2[p]) { v3[p] = v2[p]; v2[p] = v; i2[p] = o; }
                    else if (v > v3[p]) { v3[p] = v; }
                }
            }
        }

        __syncthreads();   // all threads done reading buf -> safe to overwrite
        if (it + 2 < NIT)
            issue_w(sb, wtsrc, wqsrc, swsrc, it + 2, buf, tid);
    }

    // ---- reduce across 16 tx lanes, decide / flag ----
#pragma unroll
    for (int p = 0; p < 4; p++) {
        float a1 = v1[p], a2 = v2[p], a3 = v3[p]; int j1 = i1[p], j2 = i2[p];
        float af = fv[p]; int jf = fi[p];
#pragma unroll
        for (int off = 1; off <= 8; off <<= 1) {
            float b1 = __shfl_xor_sync(0xffffffffu, a1, off);
            float b2 = __shfl_xor_sync(0xffffffffu, a2, off);
            float b3 = __shfl_xor_sync(0xffffffffu, a3, off);
            int   k1 = __shfl_xor_sync(0xffffffffu, j1, off);
            int   k2 = __shfl_xor_sync(0xffffffffu, j2, off);
            merge3(a1, a2, a3, j1, j2, b1, b2, b3, k1, k2);
            float bf = __shfl_xor_sync(0xffffffffu, af, off);
            int   kf = __shfl_xor_sync(0xffffffffu, jf, off);
            if (bf > af || (bf == af && kf < jf)) { af = bf; jf = kf; }
        }
        if (tx == 0) {
            const int t = t0 + ty * 4 + p;
            const int pair = t * NHEADS + h;
            const float sx = ((const float*)(sm + SM_SXS))[ty * 4 + p];
            float q1 = a1 * sx, q2 = a2 * sx, q3 = a3 * sx;
            const float M = fmaxf(af, q1);
            int idx = jf;
            if (q1 <= af - TH) {
                // fp32 winner certain
            } else if (q3 >= M - TH) {
                unsigned q = atomicAdd(&g_r2n[h], 1u);
                if (q < R2CAP) { g_r2[h][q] = t; g_best[pair] = 0ULL; }
            } else if (af <= q1 - TH && q2 < M - TH) {
                idx = j1;
            } else {
                unsigned has2 = (q2 >= M - TH) ? 1u : 0u;
                unsigned qq = atomicAdd(&g_r1n, 1u);
                g_r1[qq] = make_uint2((unsigned)pair,
                                      (unsigned)jf | ((unsigned)j1 << 10) |
                                      ((unsigned)j2 << 20) | (has2 << 30));
            }
            g_idx[pair] = idx;
        }
    }
}

// ---------------- tier-1 rescue ----------------
__global__ __launch_bounds__(256) void rescue1_kernel(const float* __restrict__ x,
                                                      const float* __restrict__ w) {
    const unsigned cnt = g_r1n;
    const int l = threadIdx.x & 31;
    const int gw = (blockIdx.x * 256 + threadIdx.x) >> 5;
    for (unsigned e = gw; e < cnt; e += 2048) {
        uint2 ent = g_r1[e];
        int pair = (int)ent.x, t = pair >> 4, h = pair & 15;
        int c0 = (int)(ent.y & 0x3FF);
        int c1 = (int)((ent.y >> 10) & 0x3FF);
        int c2 = (int)((ent.y >> 20) & 0x3FF);
        bool has2 = (ent.y >> 30) != 0;
        float4 xv = ((const float4*)(x + (size_t)t * EDIM + h * KD))[l];
        float4 w0 = ((const float4*)(w + ((size_t)h * OD + c0) * KD))[l];
        float4 w1 = ((const float4*)(w + ((size_t)h * OD + c1) * KD))[l];
        float4 w2 = ((const float4*)(w + ((size_t)h * OD + c2) * KD))[l];
        float d0 = xv.x * w0.x + xv.y * w0.y + xv.z * w0.z + xv.w * w0.w;
        float d1 = xv.x * w1.x + xv.y * w1.y + xv.z * w1.z + xv.w * w1.w;
        float d2 = xv.x * w2.x + xv.y * w2.y + xv.z * w2.z + xv.w * w2.w;
#pragma unroll
        for (int off = 16; off; off >>= 1) {
            d0 += __shfl_xor_sync(0xffffffffu, d0, off);
            d1 += __shfl_xor_sync(0xffffffffu, d1, off);
            d2 += __shfl_xor_sync(0xffffffffu, d2, off);
        }
        if (l == 0) {
            float bd = d0; int bi = c0;
            if (d1 > bd || (d1 == bd && c1 < bi)) { bd = d1; bi = c1; }
            if (has2 && (d2 > bd || (d2 == bd && c2 < bi))) { bd = d2; bi = c2; }
            g_idx[pair] = bi;
        }
    }
}

// ---------------- tier-2 rescue (exact full recompute, coalesced w from g_wt) ----------------
__global__ __launch_bounds__(256) void rescue2_kernel(const float* __restrict__ x) {
    __shared__ __align__(16) float xs[128][36];
    __shared__ int toks[32];
    const int h = blockIdx.x, c = blockIdx.y, slab = blockIdx.z;
    unsigned n = g_r2n[h]; if (n > R2CAP) n = R2CAP;
    const int e0 = slab * 32;
    if (e0 >= (int)n) return;
    const int cnt = ((int)n - e0 < 32) ? ((int)n - e0) : 32;
    const int tid = threadIdx.x;

    if (tid < cnt) toks[tid] = g_r2[h][e0 + tid];
    __syncthreads();
    for (int i = tid; i < cnt * 32; i += 256) {
        int e = i >> 5, k4 = i & 31;
        float4 v = ((const float4*)(x + (size_t)toks[e] * EDIM + h * KD))[k4];
        xs[k4*4+0][e] = v.x; xs[k4*4+1][e] = v.y;
        xs[k4*4+2][e] = v.z; xs[k4*4+3][e] = v.w;
    }
    __syncthreads();

    const int ol = tid & 127, tg = tid >> 7;
    const int o = c * 128 + ol;
    const float* wcol = g_wt + (size_t)h * KD * OD + o;

    float acc[16];
#pragma unroll
    for (int u = 0; u < 16; u++) acc[u] = 0.f;

#pragma unroll 4
    for (int k = 0; k < KD; k++) {
        float wv = wcol[(size_t)k * OD];
        float4 x0 = *(const float4*)&xs[k][tg * 16];
        float4 x1 = *(const float4*)&xs[k][tg * 16 + 4];
        float4 x2 = *(const float4*)&xs[k][tg * 16 + 8];
        float4 x3 = *(const float4*)&xs[k][tg * 16 + 12];
        acc[0]  += wv * x0.x; acc[1]  += wv * x0.y; acc[2]  += wv * x0.z; acc[3]  += wv * x0.w;
        acc[4]  += wv * x1.x; acc[5]  += wv * x1.y; acc[6]  += wv * x1.z; acc[7]  += wv * x1.w;
        acc[8]  += wv * x2.x; acc[9]  += wv * x2.y; acc[10] += wv * x2.z; acc[11] += wv * x2.w;
        acc[12] += wv * x3.x; acc[13] += wv * x3.y; acc[14] += wv * x3.z; acc[15] += wv * x3.w;
    }

#pragma unroll
    for (int u = 0; u < 16; u++) {
        float v = acc[u]; int oo = o;
#pragma unroll
        for (int off = 16; off; off >>= 1) {
            float v2 = __shfl_xor_sync(0xffffffffu, v, off);
            int   o2 = __shfl_xor_sync(0xffffffffu, oo, off);
            if (v2 > v || (v2 == v && o2 < oo)) { v = v2; oo = o2; }
        }
        int te = tg * 16 + u;
        if ((tid & 31) == 0 && te < cnt) {
            u64 key = ((u64)enc_f(v) << 32) | (unsigned)(OD - 1 - oo);
            atomicMax(&g_best[toks[te] * NHEADS + h], key);
        }
    }
}

__global__ void decode_kernel() {
    const int h = blockIdx.x;
    unsigned n = g_r2n[h]; if (n > R2CAP) n = R2CAP;
    for (unsigned e = threadIdx.x; e < n; e += blockDim.x) {
        int pair = g_r2[h][e] * NHEADS + h;
        u64 key = g_best[pair];
        g_idx[pair] = (OD - 1) - (int)(key & 0xFFFFFFFFULL);
    }
}

// ---------------- gather ----------------
__global__ __launch_bounds__(256) void gather_kernel(const float* __restrict__ cb,
                                                     float* __restrict__ out) {
    const float4* cb4 = (const float4*)cb;
    float4* out4 = (float4*)out;
    int q = blockIdx.x * blockDim.x + threadIdx.x;
    int t = q >> 9, r = q & 511;
    int h = r >> 5, j = r & 31;
    int bi = g_idx[t * NHEADS + h];
    out4[(size_t)t * (EDIM / 4) + h * (KD / 4) + j] =
        cb4[((size_t)h * OD + bi) * (KD / 4) + j];
}

extern "C" void kernel_launch(void* const* d_in, const int* in_sizes, int n_in,
                              void* d_out, int out_size) {
    const float* x  = (const float*)d_in[0];
    const float* w  = (const float*)d_in[1];
    const float* cb = (const float*)d_in[2];
    // d_in[3] temperature: mathematically irrelevant in the forward pass.
    float* out = (float*)d_out;

    cudaFuncSetAttribute(vq_hybrid_kernel,
                         cudaFuncAttributeMaxDynamicSharedMemorySize, SM_TOT);

    prep_w_kernel<<<dim3(OD / 32, NHEADS), 256>>>(w);
    vq_hybrid_kernel<<<dim3(NTOK / TM, NHEADS), NTHR, SM_TOT>>>(x);
    rescue1_kernel<<<256, 256>>>(x, w);
    rescue2_kernel<<<dim3(NHEADS, 8, R2CAP / 32), 256>>>(x);
    decode_kernel<<<NHEADS, 256>>>();
    gather_kernel<<<(NTOK * EDIM / 4) / 256, 256>>>(cb, out);
}

// round 16
// speedup vs baseline: 1.4655x; 1.4655x over previous
#include <cuda_runtime.h>
#include <cstdint>

#define NHEADS 16
#define OD     1024
#define OF     768        // fp32-exact options [0,768)
#define OI     256        // int8 options [768,1024)
#define KD     128
#define NK4    32
#define NTOK   4096
#define EDIM   2048
#define TM     64         // tokens per main block
#define NTHR   256
#define CWF    96         // fp32 options per iter
#define CWQ    32         // int8 options per iter
#define NIT    8
#define TH     0.032f
#define NEG_INF (-3.402823466e38f)
#define R2CAP  1024

typedef unsigned long long u64;

// ---------------- device scratch ----------------
__device__ __align__(16) float g_wt[(size_t)NHEADS*KD*OD];   // [h][k][o] fp32 transposed
__device__ __align__(16) int   g_wq[(size_t)NHEADS*NK4*OI];  // [h][k4][o-768] packed int8
__device__ __align__(16) float g_sw[NHEADS*OI];
__device__ unsigned g_r1n;
__device__ uint2    g_r1[NTOK*NHEADS];
__device__ unsigned g_r2n[NHEADS];
__device__ int      g_r2[NHEADS][R2CAP];
__device__ u64      g_best[NTOK*NHEADS];

// ---------------- main-kernel smem (bytes); total 95104 -> occ 2 ----------------
// Staging [64][132] f32 = 33792B aliases WF (49152B); disjoint from XSF/WQ/XQ.
#define SM_XSF 0                        // f32 [128 k][64 tok]          (32768)
#define SM_WF  32768                    // u64 [128 k][48 pairs]        (49152)
#define SM_STG SM_WF                    // f32 [64 tok][132] staging (alias)
#define SM_WQ  81920                    // int [32 k4][32 opt]          (4096)
#define SM_XQ  86016                    // int [32 k4][64 tok]          (8192)
#define SM_SWS 94208                    // 32 f32
#define SM_SXS 94336                    // 64 f32
#define SM_INV 94592                    // 64 f32
#define SM_IDX 94848                    // 64 int
#define SM_TOT 95104

// ---------------- helpers ----------------
#define CP16(dst, src) \
    asm volatile("cp.async.cg.shared.global [%0], [%1], 16;" :: "r"(dst), "l"(src))
#define CPCOMMIT() asm volatile("cp.async.commit_group;" ::: "memory")
#define CPWAIT0()  asm volatile("cp.async.wait_group 0;" ::: "memory")

__device__ __forceinline__ uint32_t smem_u32(const void* p) {
    uint32_t a;
    asm("{ .reg .u64 t; cvta.to.shared.u64 t, %1; cvt.u32.u64 %0, t; }" : "=r"(a) : "l"(p));
    return a;
}
__device__ __forceinline__ u64 pack2(float lo, float hi) {
    u64 r; asm("mov.b64 %0, {%1, %2};" : "=l"(r) : "f"(lo), "f"(hi)); return r;
}
__device__ __forceinline__ void unpack2(u64 v, float &lo, float &hi) {
    asm("mov.b64 {%0, %1}, %2;" : "=f"(lo), "=f"(hi) : "l"(v));
}
__device__ __forceinline__ u64 ffma2(u64 a, u64 b, u64 c) {
    u64 d; asm("fma.rn.f32x2 %0, %1, %2, %3;" : "=l"(d) : "l"(a), "l"(b), "l"(c));
    return d;
}
__device__ __forceinline__ int q8(float v, float inv) {
    int a = __float2int_rn(v * inv);
    return a < -127 ? -127 : (a > 127 ? 127 : a);
}
__device__ __forceinline__ void merge3(float& a1, float& a2, float& a3, int& j1, int& j2,
                                       float b1, float b2, float b3, int k1, int k2) {
    if (b1 > a1 || (b1 == a1 && k1 < j1)) {
        float t1 = a1, t2 = a2, t3 = a3; int u1 = j1, u2 = j2;
        a1 = b1; a2 = b2; a3 = b3; j1 = k1; j2 = k2;
        b1 = t1; b2 = t2; b3 = t3; k1 = u1; k2 = u2;
    }
    if (b1 > a2 || (b1 == a2 && k1 < j2)) { a3 = fmaxf(a2, b2); a2 = b1; j2 = k1; }
    else                                  { a3 = fmaxf(a3, b1); }
}
__device__ __forceinline__ unsigned enc_f(float f) {
    unsigned u = __float_as_uint(f);
    return (u & 0x80000000u) ? ~u : (u | 0x80000000u);
}

// ---------------- w preprocessing ----------------
__global__ __launch_bounds__(256) void prep_w_kernel(const float* __restrict__ w) {
    __shared__ float trf[128 * 33];
    __shared__ float sws_s[32], invs[32];
    if (blockIdx.x == 0 && blockIdx.y == 0) {
        if (threadIdx.x == 0) g_r1n = 0;
        if (threadIdx.x < NHEADS) g_r2n[threadIdx.x] = 0;
    }
    const int h = blockIdx.y, o0 = blockIdx.x * 32;
    const int tid = threadIdx.x, l = tid & 31, wid = tid >> 5;

    for (int r = wid; r < 32; r += 8) {
        float4 v = *(const float4*)(w + ((size_t)h * OD + o0 + r) * KD + l * 4);
        trf[(4*l+0)*33 + r] = v.x; trf[(4*l+1)*33 + r] = v.y;
        trf[(4*l+2)*33 + r] = v.z; trf[(4*l+3)*33 + r] = v.w;
        if (o0 >= OF) {
            float mx = fmaxf(fmaxf(fabsf(v.x), fabsf(v.y)), fmaxf(fabsf(v.z), fabsf(v.w)));
#pragma unroll
            for (int off = 16; off; off >>= 1)
                mx = fmaxf(mx, __shfl_xor_sync(0xffffffffu, mx, off));
            if (l == 0) {
                sws_s[r] = mx * (1.f / 127.f);
                invs[r]  = (mx > 0.f) ? 127.f / mx : 0.f;
            }
        }
    }
    __syncthreads();
    for (int i = tid; i < 4096; i += 256) {
        int k = i >> 5, rl = i & 31;
        g_wt[((size_t)h * KD + k) * OD + o0 + rl] = trf[k * 33 + rl];
    }
    if (o0 >= OF) {
        for (int i = tid; i < 1024; i += 256) {
            int k4 = i >> 5, rl = i & 31;
            float inv = invs[rl];
            int a0 = q8(trf[(4*k4+0)*33 + rl], inv);
            int a1 = q8(trf[(4*k4+1)*33 + rl], inv);
            int a2 = q8(trf[(4*k4+2)*33 + rl], inv);
            int a3 = q8(trf[(4*k4+3)*33 + rl], inv);
            g_wq[((size_t)h * NK4 + k4) * OI + (o0 - OF) + rl] =
                (a0 & 255) | ((a1 & 255) << 8) | ((a2 & 255) << 16) | ((a3 & 255) << 24);
        }
        if (tid < 32) g_sw[h * OI + (o0 - OF) + tid] = sws_s[tid];
    }
}

// ---------------- main: 64 tok x 1 head, 256 threads, occ 2, fused gather ----------------
// 16 tx x 16 ty; thread tile = 4 tokens x (6 fp32 + 2 int8) options per iter
__global__ __launch_bounds__(NTHR, 2) void vq_hybrid_kernel(const float* __restrict__ x,
                                                            const float* __restrict__ cb,
                                                            float* __restrict__ out) {
    extern __shared__ char sm[];
    const uint32_t sb = smem_u32(sm);
    const int tid = threadIdx.x, l = tid & 31, wrp = tid >> 5;
    const int tx = tid & 15, ty = tid >> 4;
    const int t0 = blockIdx.x * TM, h = blockIdx.y;

    const float* wtsrc = g_wt + (size_t)h * KD * OD;
    const int*   wqsrc = g_wq + (size_t)h * NK4 * OI;
    const float* swsrc = g_sw + (size_t)h * OI;

    // ---- prologue: 64 tokens ----
    {
        float* stg = (float*)(sm + SM_STG);        // [64][132]
        float* sxs = (float*)(sm + SM_SXS);
        float* inv = (float*)(sm + SM_INV);
        float* xsf = (float*)(sm + SM_XSF);
        int*   xq  = (int*)(sm + SM_XQ);
#pragma unroll
        for (int rr = 0; rr < 8; rr++) {
            int tl = wrp * 8 + rr;
            float4 v = *(const float4*)(x + (size_t)(t0 + tl) * EDIM + h * KD + l * 4);
            float mx = fmaxf(fmaxf(fabsf(v.x), fabsf(v.y)), fmaxf(fabsf(v.z), fabsf(v.w)));
#pragma unroll
            for (int off = 16; off; off >>= 1)
                mx = fmaxf(mx, __shfl_xor_sync(0xffffffffu, mx, off));
            if (l == 0) {
                sxs[tl] = mx * (1.f / 127.f);
                inv[tl] = (mx > 0.f) ? 127.f / mx : 0.f;
            }
            *(float4*)&stg[tl * 132 + l * 4] = v;
        }
        __syncthreads();
        {
            const int t = tid & 63;
            const float invv = inv[t];
#pragma unroll
            for (int r = 0; r < 8; r++) {
                int k4 = (tid >> 6) + 4 * r;       // 0..31
                float4 f = *(const float4*)&stg[t * 132 + 4 * k4];
                xsf[(4*k4+0) * TM + t] = f.x;
                xsf[(4*k4+1) * TM + t] = f.y;
                xsf[(4*k4+2) * TM + t] = f.z;
                xsf[(4*k4+3) * TM + t] = f.w;
                int a0 = q8(f.x, invv), a1 = q8(f.y, invv);
                int a2 = q8(f.z, invv), a3 = q8(f.w, invv);
                xq[k4 * TM + t] =
                    (a0 & 255) | ((a1 & 255) << 8) | ((a2 & 255) << 16) | ((a3 & 255) << 24);
            }
        }
    }

    float fv[4]; int fi[4];
    float v1[4], v2[4], v3[4]; int i1[4], i2[4];
#pragma unroll
    for (int p = 0; p < 4; p++) {
        fv[p] = NEG_INF; fi[p] = 0;
        v1[p] = v2[p] = v3[p] = NEG_INF; i1[p] = OF; i2[p] = OF;
    }

#pragma unroll 1
    for (int it = 0; it < NIT; it++) {
        __syncthreads();   // prev iter consumed; it=0: prologue done (STG alias safe)
        // WF: [k][48 pairs] = 3072 16B-vectors (12/thread)
#pragma unroll
        for (int r = 0; r < 12; r++) {
            int i = tid + NTHR * r;
            int k = i / 24, v = i % 24;
            CP16(sb + SM_WF + k * 384 + v * 16,
                 wtsrc + (size_t)k * OD + it * CWF + v * 4);
        }
        {   // WQ: 256 vectors
            int k4 = tid >> 3, s = tid & 7;
            CP16(sb + SM_WQ + k4 * 128 + s * 16,
                 wqsrc + (size_t)k4 * OI + it * CWQ + s * 4);
        }
        if (tid < 8)
            CP16(sb + SM_SWS + tid * 16, swsrc + it * CWQ + tid * 4);
        CPCOMMIT(); CPWAIT0();
        __syncthreads();

        u64 facc[4][3];
        int iacc[4][2];
#pragma unroll
        for (int p = 0; p < 4; p++) {
            facc[p][0] = facc[p][1] = facc[p][2] = 0ULL;
            iacc[p][0] = iacc[p][1] = 0;
        }

#pragma unroll 2
        for (int k4 = 0; k4 < NK4; k4++) {
            int4 xqv = *(const int4*)(sm + SM_XQ + (k4 * TM + ty * 4) * 4);
            int2 wqv = *(const int2*)(sm + SM_WQ + (k4 * 32 + tx * 2) * 4);
            iacc[0][0] = __dp4a(xqv.x, wqv.x, iacc[0][0]);
            iacc[0][1] = __dp4a(xqv.x, wqv.y, iacc[0][1]);
            iacc[1][0] = __dp4a(xqv.y, wqv.x, iacc[1][0]);
            iacc[1][1] = __dp4a(xqv.y, wqv.y, iacc[1][1]);
            iacc[2][0] = __dp4a(xqv.z, wqv.x, iacc[2][0]);
            iacc[2][1] = __dp4a(xqv.z, wqv.y, iacc[2][1]);
            iacc[3][0] = __dp4a(xqv.w, wqv.x, iacc[3][0]);
            iacc[3][1] = __dp4a(xqv.w, wqv.y, iacc[3][1]);
#pragma unroll
            for (int j = 0; j < 4; j++) {
                const int k = k4 * 4 + j;
                float4 xf = *(const float4*)(sm + SM_XSF + (k * TM + ty * 4) * 4);
                u64 xp0 = pack2(xf.x, xf.x);
                u64 xp1 = pack2(xf.y, xf.y);
                u64 xp2 = pack2(xf.z, xf.z);
                u64 xp3 = pack2(xf.w, xf.w);
                u64 w0 = *(const u64*)(sm + SM_WF + (k * 48 + tx) * 8);
                u64 w1 = *(const u64*)(sm + SM_WF + (k * 48 + tx + 16) * 8);
                u64 w2 = *(const u64*)(sm + SM_WF + (k * 48 + tx + 32) * 8);
                facc[0][0] = ffma2(xp0, w0, facc[0][0]);
                facc[0][1] = ffma2(xp0, w1, facc[0][1]);
                facc[0][2] = ffma2(xp0, w2, facc[0][2]);
                facc[1][0] = ffma2(xp1, w0, facc[1][0]);
                facc[1][1] = ffma2(xp1, w1, facc[1][1]);
                facc[1][2] = ffma2(xp1, w2, facc[1][2]);
                facc[2][0] = ffma2(xp2, w0, facc[2][0]);
                facc[2][1] = ffma2(xp2, w1, facc[2][1]);
                facc[2][2] = ffma2(xp2, w2, facc[2][2]);
                facc[3][0] = ffma2(xp3, w0, facc[3][0]);
                facc[3][1] = ffma2(xp3, w1, facc[3][1]);
                facc[3][2] = ffma2(xp3, w2, facc[3][2]);
            }
        }

        // fold fp32 (exact top-1; o ascending in s for fixed thread)
#pragma unroll
        for (int p = 0; p < 4; p++) {
#pragma unroll
            for (int s = 0; s < 3; s++) {
                const int o = it * CWF + (tx + 16 * s) * 2;
                float q0, q1; unpack2(facc[p][s], q0, q1);
                if (q0 > fv[p]) { fv[p] = q0; fi[p] = o; }
                if (q1 > fv[p]) { fv[p] = q1; fi[p] = o + 1; }
            }
        }
        // fold int8 (top-3)
        {
            float2 s2 = *(const float2*)(sm + SM_SWS + tx * 8);
            const int ob = OF + it * CWQ + tx * 2;
#pragma unroll
            for (int p = 0; p < 4; p++) {
#pragma unroll
                for (int u = 0; u < 2; u++) {
                    float v = (float)iacc[p][u] * (u ? s2.y : s2.x);
                    int o = ob + u;
                    if (v > v1[p]) { v3[p] = v2[p]; v2[p] = v1[p]; i2[p] = i1[p]; v1[p] = v; i1[p] = o; }
                    else if (v > v2[p]) { v3[p] = v2[p]; v2[p] = v; i2[p] = o; }
                    else if (v > v3[p]) { v3[p] = v; }
                }
            }
        }
    }

    // ---- reduce across 16 tx lanes, decide / flag; idx -> smem ----
    int* idxs = (int*)(sm + SM_IDX);
#pragma unroll
    for (int p = 0; p < 4; p++) {
        float a1 = v1[p], a2 = v2[p], a3 = v3[p]; int j1 = i1[p], j2 = i2[p];
        float af = fv[p]; int jf = fi[p];
#pragma unroll
        for (int off = 1; off <= 8; off <<= 1) {
            float b1 = __shfl_xor_sync(0xffffffffu, a1, off);
            float b2 = __shfl_xor_sync(0xffffffffu, a2, off);
            float b3 = __shfl_xor_sync(0xffffffffu, a3, off);
            int   k1 = __shfl_xor_sync(0xffffffffu, j1, off);
            int   k2 = __shfl_xor_sync(0xffffffffu, j2, off);
            merge3(a1, a2, a3, j1, j2, b1, b2, b3, k1, k2);
            float bf = __shfl_xor_sync(0xffffffffu, af, off);
            int   kf = __shfl_xor_sync(0xffffffffu, jf, off);
            if (bf > af || (bf == af && kf < jf)) { af = bf; jf = kf; }
        }
        if (tx == 0) {
            const int t = t0 + ty * 4 + p;
            const int pair = t * NHEADS + h;
            const float sx = ((const float*)(sm + SM_SXS))[ty * 4 + p];
            float q1 = a1 * sx, q2 = a2 * sx, q3 = a3 * sx;
            const float M = fmaxf(af, q1);
            int idx = jf;
            if (q1 <= af - TH) {
                // fp32 winner certain
            } else if (q3 >= M - TH) {
                unsigned q = atomicAdd(&g_r2n[h], 1u);
                if (q < R2CAP) { g_r2[h][q] = t; g_best[pair] = 0ULL; }
            } else if (af <= q1 - TH && q2 < M - TH) {
                idx = j1;
            } else {
                unsigned has2 = (q2 >= M - TH) ? 1u : 0u;
                unsigned qq = atomicAdd(&g_r1n, 1u);
                g_r1[qq] = make_uint2((unsigned)pair,
                                      (unsigned)jf | ((unsigned)j1 << 10) |
                                      ((unsigned)j2 << 20) | (has2 << 30));
            }
            idxs[ty * 4 + p] = idx;
        }
    }
    __syncthreads();

    // ---- fused gather: out[t, h*128:+128] = cb[h, idx[t], :] ----
    {
        const float4* cb4 = (const float4*)cb;
        float4* out4 = (float4*)out;
        for (int q = tid; q < TM * (KD / 4); q += NTHR) {
            int t = q >> 5, j = q & 31;
            out4[(size_t)(t0 + t) * (EDIM / 4) + h * (KD / 4) + j] =
                cb4[((size_t)h * OD + idxs[t]) * (KD / 4) + j];
        }
    }
}

// ---------------- tier-1 rescue: exact compare + direct row write ----------------
__global__ __launch_bounds__(256) void rescue1_kernel(const float* __restrict__ x,
                                                      const float* __restrict__ w,
                                                      const float* __restrict__ cb,
                                                      float* __restrict__ out) {
    const unsigned cnt = g_r1n;
    const int l = threadIdx.x & 31;
    const int gw = (blockIdx.x * 256 + threadIdx.x) >> 5;
    for (unsigned e = gw; e < cnt; e += 2048) {
        uint2 ent = g_r1[e];
        int pair = (int)ent.x, t = pair >> 4, h = pair & 15;
        int c0 = (int)(ent.y & 0x3FF);
        int c1 = (int)((ent.y >> 10) & 0x3FF);
        int c2 = (int)((ent.y >> 20) & 0x3FF);
        bool has2 = ((ent.y >> 30) & 1) != 0;
        float4 xv = ((const float4*)(x + (size_t)t * EDIM + h * KD))[l];
        float4 w0 = ((const float4*)(w + ((size_t)h * OD + c0) * KD))[l];
        float4 w1 = ((const float4*)(w + ((size_t)h * OD + c1) * KD))[l];
        float4 w2 = ((const float4*)(w + ((size_t)h * OD + c2) * KD))[l];
        float d0 = xv.x * w0.x + xv.y * w0.y + xv.z * w0.z + xv.w * w0.w;
        float d1 = xv.x * w1.x + xv.y * w1.y + xv.z * w1.z + xv.w * w1.w;
        float d2 = xv.x * w2.x + xv.y * w2.y + xv.z * w2.z + xv.w * w2.w;
#pragma unroll
        for (int off = 16; off; off >>= 1) {
            d0 += __shfl_xor_sync(0xffffffffu, d0, off);
            d1 += __shfl_xor_sync(0xffffffffu, d1, off);
            d2 += __shfl_xor_sync(0xffffffffu, d2, off);
        }
        // all lanes hold identical sums after xor-reduction
        float bd = d0; int bi = c0;
        if (d1 > bd || (d1 == bd && c1 < bi)) { bd = d1; bi = c1; }
        if (has2 && (d2 > bd || (d2 == bd && c2 < bi))) { bd = d2; bi = c2; }
        ((float4*)out)[(size_t)t * (EDIM / 4) + h * (KD / 4) + l] =
            ((const float4*)cb)[((size_t)h * OD + bi) * (KD / 4) + l];
    }
}

// ---------------- tier-2 rescue: slab loop inside (128 blocks total) ----------------
__global__ __launch_bounds__(256) void rescue2_kernel(const float* __restrict__ x) {
    __shared__ __align__(16) float xs[128][36];
    __shared__ int toks[32];
    const int h = blockIdx.x, c = blockIdx.y;
    unsigned n = g_r2n[h]; if (n > R2CAP) n = R2CAP;
    const int tid = threadIdx.x;
    const int ol = tid & 127, tg = tid >> 7;
    const int o = c * 128 + ol;
    const float* wcol = g_wt + (size_t)h * KD * OD + o;

    for (int e0 = 0; e0 < (int)n; e0 += 32) {
        const int cnt = ((int)n - e0 < 32) ? ((int)n - e0) : 32;
        __syncthreads();   // previous slab fully consumed
        if (tid < cnt) toks[tid] = g_r2[h][e0 + tid];
        __syncthreads();
        for (int i = tid; i < cnt * 32; i += 256) {
            int e = i >> 5, k4 = i & 31;
            float4 v = ((const float4*)(x + (size_t)toks[e] * EDIM + h * KD))[k4];
            xs[k4*4+0][e] = v.x; xs[k4*4+1][e] = v.y;
            xs[k4*4+2][e] = v.z; xs[k4*4+3][e] = v.w;
        }
        __syncthreads();

        float acc[16];
#pragma unroll
        for (int u = 0; u < 16; u++) acc[u] = 0.f;
#pragma unroll 4
        for (int k = 0; k < KD; k++) {
            float wv = wcol[(size_t)k * OD];
            float4 x0 = *(const float4*)&xs[k][tg * 16];
            float4 x1 = *(const float4*)&xs[k][tg * 16 + 4];
            float4 x2 = *(const float4*)&xs[k][tg * 16 + 8];
            float4 x3 = *(const float4*)&xs[k][tg * 16 + 12];
            acc[0]  += wv * x0.x; acc[1]  += wv * x0.y; acc[2]  += wv * x0.z; acc[3]  += wv * x0.w;
            acc[4]  += wv * x1.x; acc[5]  += wv * x1.y; acc[6]  += wv * x1.z; acc[7]  += wv * x1.w;
            acc[8]  += wv * x2.x; acc[9]  += wv * x2.y; acc[10] += wv * x2.z; acc[11] += wv * x2.w;
            acc[12] += wv * x3.x; acc[13] += wv * x3.y; acc[14] += wv * x3.z; acc[15] += wv * x3.w;
        }
#pragma unroll
        for (int u = 0; u < 16; u++) {
            float v = acc[u]; int oo = o;
#pragma unroll
            for (int off = 16; off; off >>= 1) {
                float v2 = __shfl_xor_sync(0xffffffffu, v, off);
                int   o2 = __shfl_xor_sync(0xffffffffu, oo, off);
                if (v2 > v || (v2 == v && o2 < oo)) { v = v2; oo = o2; }
            }
            int te = tg * 16 + u;
            if ((tid & 31) == 0 && te < cnt) {
                u64 key = ((u64)enc_f(v) << 32) | (unsigned)(OD - 1 - oo);
                atomicMax(&g_best[toks[te] * NHEADS + h], key);
            }
        }
    }
}

// decode tier-2 winners and write output rows directly
__global__ void decode_kernel(const float* __restrict__ cb, float* __restrict__ out) {
    const int h = blockIdx.x;
    unsigned n = g_r2n[h]; if (n > R2CAP) n = R2CAP;
    const int wid = threadIdx.x >> 5, l = threadIdx.x & 31;
    for (unsigned e = wid; e < n; e += 8) {
        int t = g_r2[h][e];
        u64 key = g_best[t * NHEADS + h];
        int bi = (OD - 1) - (int)(key & 0xFFFFFFFFULL);
        ((float4*)out)[(size_t)t * (EDIM / 4) + h * (KD / 4) + l] =
            ((const float4*)cb)[((size_t)h * OD + bi) * (KD / 4) + l];
    }
}

extern "C" void kernel_launch(void* const* d_in, const int* in_sizes, int n_in,
                              void* d_out, int out_size) {
    const float* x  = (const float*)d_in[0];
    const float* w  = (const float*)d_in[1];
    const float* cb = (const float*)d_in[2];
    // d_in[3] temperature: mathematically irrelevant in the forward pass.
    float* out = (float*)d_out;

    cudaFuncSetAttribute(vq_hybrid_kernel,
                         cudaFuncAttributeMaxDynamicSharedMemorySize, SM_TOT);

    prep_w_kernel<<<dim3(OD / 32, NHEADS), 256>>>(w);
    vq_hybrid_kernel<<<dim3(NTOK / TM, NHEADS), NTHR, SM_TOT>>>(x, cb, out);
    rescue1_kernel<<<256, 256>>>(x, w, cb, out);
    rescue2_kernel<<<dim3(NHEADS, 8), 256>>>(x);
    decode_kernel<<<NHEADS, 256>>>(cb, out);
}

// round 17
// speedup vs baseline: 1.5060x; 1.0276x over previous
#include <cuda_runtime.h>
#include <cstdint>

#define NHEADS 16
#define OD     1024
#define OF     768        // fp32-exact options [0,768)
#define OI     256        // int8 options [768,1024)
#define KD     128
#define NK4    32
#define NTOK   4096
#define EDIM   2048
#define TM     64         // tokens per main block
#define NTHR   256
#define CWF    96         // fp32 options per iter
#define CWQ    32         // int8 options per iter
#define NIT    8
#define TH     0.032f
#define NEG_INF (-3.402823466e38f)
#define R2CAP  1024

typedef unsigned long long u64;

// ---------------- device scratch ----------------
__device__ __align__(16) float g_wt[(size_t)NHEADS*KD*OD];   // [h][k][o] fp32 transposed
__device__ __align__(16) int   g_wq[(size_t)NHEADS*NK4*OI];  // [h][k4][o-768] packed int8
__device__ __align__(16) float g_sw[NHEADS*OI];
__device__ unsigned g_r1n;
__device__ uint2    g_r1[NTOK*NHEADS];
__device__ unsigned g_r2n[NHEADS];
__device__ int      g_r2[NHEADS][R2CAP];
__device__ u64      g_best[NTOK*NHEADS];

// ---------------- main-kernel smem (bytes); total 95104 -> occ 2 ----------------
// Staging [64][132] f32 = 33792B aliases WF (49152B); disjoint from XSF/WQ/XQ.
#define SM_XSF 0                        // f32 [128 k][64 tok]          (32768)
#define SM_WF  32768                    // u64 [128 k][48 pairs]        (49152)
#define SM_STG SM_WF                    // f32 [64 tok][132] staging (alias)
#define SM_WQ  81920                    // int [32 k4][32 opt]          (4096)
#define SM_XQ  86016                    // int [32 k4][64 tok]          (8192)
#define SM_SWS 94208                    // 32 f32
#define SM_SXS 94336                    // 64 f32
#define SM_INV 94592                    // 64 f32
#define SM_IDX 94848                    // 64 int
#define SM_TOT 95104

// ---------------- helpers ----------------
#define CP16(dst, src) \
    asm volatile("cp.async.cg.shared.global [%0], [%1], 16;" :: "r"(dst), "l"(src))
#define CPCOMMIT() asm volatile("cp.async.commit_group;" ::: "memory")
#define CPWAIT0()  asm volatile("cp.async.wait_group 0;" ::: "memory")

__device__ __forceinline__ uint32_t smem_u32(const void* p) {
    uint32_t a;
    asm("{ .reg .u64 t; cvta.to.shared.u64 t, %1; cvt.u32.u64 %0, t; }" : "=r"(a) : "l"(p));
    return a;
}
__device__ __forceinline__ u64 pack2(float lo, float hi) {
    u64 r; asm("mov.b64 %0, {%1, %2};" : "=l"(r) : "f"(lo), "f"(hi)); return r;
}
__device__ __forceinline__ void unpack2(u64 v, float &lo, float &hi) {
    asm("mov.b64 {%0, %1}, %2;" : "=f"(lo), "=f"(hi) : "l"(v));
}
__device__ __forceinline__ u64 ffma2(u64 a, u64 b, u64 c) {
    u64 d; asm("fma.rn.f32x2 %0, %1, %2, %3;" : "=l"(d) : "l"(a), "l"(b), "l"(c));
    return d;
}
__device__ __forceinline__ int q8(float v, float inv) {
    int a = __float2int_rn(v * inv);
    return a < -127 ? -127 : (a > 127 ? 127 : a);
}
__device__ __forceinline__ void merge3(float& a1, float& a2, float& a3, int& j1, int& j2,
                                       float b1, float b2, float b3, int k1, int k2) {
    if (b1 > a1 || (b1 == a1 && k1 < j1)) {
        float t1 = a1, t2 = a2, t3 = a3; int u1 = j1, u2 = j2;
        a1 = b1; a2 = b2; a3 = b3; j1 = k1; j2 = k2;
        b1 = t1; b2 = t2; b3 = t3; k1 = u1; k2 = u2;
    }
    if (b1 > a2 || (b1 == a2 && k1 < j2)) { a3 = fmaxf(a2, b2); a2 = b1; j2 = k1; }
    else                                  { a3 = fmaxf(a3, b1); }
}
__device__ __forceinline__ unsigned enc_f(float f) {
    unsigned u = __float_as_uint(f);
    return (u & 0x80000000u) ? ~u : (u | 0x80000000u);
}

// ---------------- w preprocessing ----------------
__global__ __launch_bounds__(256) void prep_w_kernel(const float* __restrict__ w) {
    __shared__ float trf[128 * 33];
    __shared__ float sws_s[32], invs[32];
    if (blockIdx.x == 0 && blockIdx.y == 0) {
        if (threadIdx.x == 0) g_r1n = 0;
        if (threadIdx.x < NHEADS) g_r2n[threadIdx.x] = 0;
    }
    const int h = blockIdx.y, o0 = blockIdx.x * 32;
    const int tid = threadIdx.x, l = tid & 31, wid = tid >> 5;

    for (int r = wid; r < 32; r += 8) {
        float4 v = *(const float4*)(w + ((size_t)h * OD + o0 + r) * KD + l * 4);
        trf[(4*l+0)*33 + r] = v.x; trf[(4*l+1)*33 + r] = v.y;
        trf[(4*l+2)*33 + r] = v.z; trf[(4*l+3)*33 + r] = v.w;
        if (o0 >= OF) {
            float mx = fmaxf(fmaxf(fabsf(v.x), fabsf(v.y)), fmaxf(fabsf(v.z), fabsf(v.w)));
#pragma unroll
            for (int off = 16; off; off >>= 1)
                mx = fmaxf(mx, __shfl_xor_sync(0xffffffffu, mx, off));
            if (l == 0) {
                sws_s[r] = mx * (1.f / 127.f);
                invs[r]  = (mx > 0.f) ? 127.f / mx : 0.f;
            }
        }
    }
    __syncthreads();
    for (int i = tid; i < 4096; i += 256) {
        int k = i >> 5, rl = i & 31;
        g_wt[((size_t)h * KD + k) * OD + o0 + rl] = trf[k * 33 + rl];
    }
    if (o0 >= OF) {
        for (int i = tid; i < 1024; i += 256) {
            int k4 = i >> 5, rl = i & 31;
            float inv = invs[rl];
            int a0 = q8(trf[(4*k4+0)*33 + rl], inv);
            int a1 = q8(trf[(4*k4+1)*33 + rl], inv);
            int a2 = q8(trf[(4*k4+2)*33 + rl], inv);
            int a3 = q8(trf[(4*k4+3)*33 + rl], inv);
            g_wq[((size_t)h * NK4 + k4) * OI + (o0 - OF) + rl] =
                (a0 & 255) | ((a1 & 255) << 8) | ((a2 & 255) << 16) | ((a3 & 255) << 24);
        }
        if (tid < 32) g_sw[h * OI + (o0 - OF) + tid] = sws_s[tid];
    }
}

// ---------------- main: 64 tok x 1 head, 256 threads, occ 2, fused gather ----------------
// 16 tx x 16 ty; thread tile = 4 tokens x (6 fp32 + 2 int8) options per iter
__global__ __launch_bounds__(NTHR, 2) void vq_hybrid_kernel(const float* __restrict__ x,
                                                            const float* __restrict__ cb,
                                                            float* __restrict__ out) {
    extern __shared__ char sm[];
    const uint32_t sb = smem_u32(sm);
    const int tid = threadIdx.x, l = tid & 31, wrp = tid >> 5;
    const int tx = tid & 15, ty = tid >> 4;
    const int t0 = blockIdx.x * TM, h = blockIdx.y;

    const float* wtsrc = g_wt + (size_t)h * KD * OD;
    const int*   wqsrc = g_wq + (size_t)h * NK4 * OI;
    const float* swsrc = g_sw + (size_t)h * OI;

    // ---- prologue: 64 tokens ----
    {
        float* stg = (float*)(sm + SM_STG);        // [64][132]
        float* sxs = (float*)(sm + SM_SXS);
        float* inv = (float*)(sm + SM_INV);
        float* xsf = (float*)(sm + SM_XSF);
        int*   xq  = (int*)(sm + SM_XQ);
#pragma unroll
        for (int rr = 0; rr < 8; rr++) {
            int tl = wrp * 8 + rr;
            float4 v = *(const float4*)(x + (size_t)(t0 + tl) * EDIM + h * KD + l * 4);
            float mx = fmaxf(fmaxf(fabsf(v.x), fabsf(v.y)), fmaxf(fabsf(v.z), fabsf(v.w)));
#pragma unroll
            for (int off = 16; off; off >>= 1)
                mx = fmaxf(mx, __shfl_xor_sync(0xffffffffu, mx, off));
            if (l == 0) {
                sxs[tl] = mx * (1.f / 127.f);
                inv[tl] = (mx > 0.f) ? 127.f / mx : 0.f;
            }
            *(float4*)&stg[tl * 132 + l * 4] = v;
        }
        __syncthreads();
        {
            const int t = tid & 63;
            const float invv = inv[t];
#pragma unroll
            for (int r = 0; r < 8; r++) {
                int k4 = (tid >> 6) + 4 * r;       // 0..31
                float4 f = *(const float4*)&stg[t * 132 + 4 * k4];
                xsf[(4*k4+0) * TM + t] = f.x;
                xsf[(4*k4+1) * TM + t] = f.y;
                xsf[(4*k4+2) * TM + t] = f.z;
                xsf[(4*k4+3) * TM + t] = f.w;
                int a0 = q8(f.x, invv), a1 = q8(f.y, invv);
                int a2 = q8(f.z, invv), a3 = q8(f.w, invv);
                xq[k4 * TM + t] =
                    (a0 & 255) | ((a1 & 255) << 8) | ((a2 & 255) << 16) | ((a3 & 255) << 24);
            }
        }
    }

    float fv[4]; int fi[4];
    float v1[4], v2[4], v3[4]; int i1[4], i2[4];
#pragma unroll
    for (int p = 0; p < 4; p++) {
        fv[p] = NEG_INF; fi[p] = 0;
        v1[p] = v2[p] = v3[p] = NEG_INF; i1[p] = OF; i2[p] = OF;
    }

#pragma unroll 1
    for (int it = 0; it < NIT; it++) {
        __syncthreads();   // prev iter consumed; it=0: prologue done (STG alias safe)
        // WF: [k][48 pairs] = 3072 16B-vectors (12/thread)
#pragma unroll
        for (int r = 0; r < 12; r++) {
            int i = tid + NTHR * r;
            int k = i / 24, v = i % 24;
            CP16(sb + SM_WF + k * 384 + v * 16,
                 wtsrc + (size_t)k * OD + it * CWF + v * 4);
        }
        {   // WQ: 256 vectors
            int k4 = tid >> 3, s = tid & 7;
            CP16(sb + SM_WQ + k4 * 128 + s * 16,
                 wqsrc + (size_t)k4 * OI + it * CWQ + s * 4);
        }
        if (tid < 8)
            CP16(sb + SM_SWS + tid * 16, swsrc + it * CWQ + tid * 4);
        CPCOMMIT(); CPWAIT0();
        __syncthreads();

        u64 facc[4][3];
        int iacc[4][2];
#pragma unroll
        for (int p = 0; p < 4; p++) {
            facc[p][0] = facc[p][1] = facc[p][2] = 0ULL;
            iacc[p][0] = iacc[p][1] = 0;
        }

#pragma unroll 4
        for (int k4 = 0; k4 < NK4; k4++) {
            int4 xqv = *(const int4*)(sm + SM_XQ + (k4 * TM + ty * 4) * 4);
            int2 wqv = *(const int2*)(sm + SM_WQ + (k4 * 32 + tx * 2) * 4);
            iacc[0][0] = __dp4a(xqv.x, wqv.x, iacc[0][0]);
            iacc[0][1] = __dp4a(xqv.x, wqv.y, iacc[0][1]);
            iacc[1][0] = __dp4a(xqv.y, wqv.x, iacc[1][0]);
            iacc[1][1] = __dp4a(xqv.y, wqv.y, iacc[1][1]);
            iacc[2][0] = __dp4a(xqv.z, wqv.x, iacc[2][0]);
            iacc[2][1] = __dp4a(xqv.z, wqv.y, iacc[2][1]);
            iacc[3][0] = __dp4a(xqv.w, wqv.x, iacc[3][0]);
            iacc[3][1] = __dp4a(xqv.w, wqv.y, iacc[3][1]);
#pragma unroll
            for (int j = 0; j < 4; j++) {
                const int k = k4 * 4 + j;
                float4 xf = *(const float4*)(sm + SM_XSF + (k * TM + ty * 4) * 4);
                u64 xp0 = pack2(xf.x, xf.x);
                u64 xp1 = pack2(xf.y, xf.y);
                u64 xp2 = pack2(xf.z, xf.z);
                u64 xp3 = pack2(xf.w, xf.w);
                u64 w0 = *(const u64*)(sm + SM_WF + (k * 48 + tx) * 8);
                u64 w1 = *(const u64*)(sm + SM_WF + (k * 48 + tx + 16) * 8);
                u64 w2 = *(const u64*)(sm + SM_WF + (k * 48 + tx + 32) * 8);
                facc[0][0] = ffma2(xp0, w0, facc[0][0]);
                facc[0][1] = ffma2(xp0, w1, facc[0][1]);
                facc[0][2] = ffma2(xp0, w2, facc[0][2]);
                facc[1][0] = ffma2(xp1, w0, facc[1][0]);
                facc[1][1] = ffma2(xp1, w1, facc[1][1]);
                facc[1][2] = ffma2(xp1, w2, facc[1][2]);
                facc[2][0] = ffma2(xp2, w0, facc[2][0]);
                facc[2][1] = ffma2(xp2, w1, facc[2][1]);
                facc[2][2] = ffma2(xp2, w2, facc[2][2]);
                facc[3][0] = ffma2(xp3, w0, facc[3][0]);
                facc[3][1] = ffma2(xp3, w1, facc[3][1]);
                facc[3][2] = ffma2(xp3, w2, facc[3][2]);
            }
        }

        // fold fp32 (exact top-1; o ascending in s for fixed thread)
#pragma unroll
        for (int p = 0; p < 4; p++) {
#pragma unroll
            for (int s = 0; s < 3; s++) {
                const int o = it * CWF + (tx + 16 * s) * 2;
                float q0, q1; unpack2(facc[p][s], q0, q1);
                if (q0 > fv[p]) { fv[p] = q0; fi[p] = o; }
                if (q1 > fv[p]) { fv[p] = q1; fi[p] = o + 1; }
            }
        }
        // fold int8 (top-3)
        {
            float2 s2 = *(const float2*)(sm + SM_SWS + tx * 8);
            const int ob = OF + it * CWQ + tx * 2;
#pragma unroll
            for (int p = 0; p < 4; p++) {
#pragma unroll
                for (int u = 0; u < 2; u++) {
                    float v = (float)iacc[p][u] * (u ? s2.y : s2.x);
                    int o = ob + u;
                    if (v > v1[p]) { v3[p] = v2[p]; v2[p] = v1[p]; i2[p] = i1[p]; v1[p] = v; i1[p] = o; }
                    else if (v > v2[p]) { v3[p] = v2[p]; v2[p] = v; i2[p] = o; }
                    else if (v > v3[p]) { v3[p] = v; }
                }
            }
        }
    }

    // ---- reduce across 16 tx lanes, decide / flag; idx -> smem ----
    int* idxs = (int*)(sm + SM_IDX);
#pragma unroll
    for (int p = 0; p < 4; p++) {
        float a1 = v1[p], a2 = v2[p], a3 = v3[p]; int j1 = i1[p], j2 = i2[p];
        float af = fv[p]; int jf = fi[p];
#pragma unroll
        for (int off = 1; off <= 8; off <<= 1) {
            float b1 = __shfl_xor_sync(0xffffffffu, a1, off);
            float b2 = __shfl_xor_sync(0xffffffffu, a2, off);
            float b3 = __shfl_xor_sync(0xffffffffu, a3, off);
            int   k1 = __shfl_xor_sync(0xffffffffu, j1, off);
            int   k2 = __shfl_xor_sync(0xffffffffu, j2, off);
            merge3(a1, a2, a3, j1, j2, b1, b2, b3, k1, k2);
            float bf = __shfl_xor_sync(0xffffffffu, af, off);
            int   kf = __shfl_xor_sync(0xffffffffu, jf, off);
            if (bf > af || (bf == af && kf < jf)) { af = bf; jf = kf; }
        }
        if (tx == 0) {
            const int t = t0 + ty * 4 + p;
            const int pair = t * NHEADS + h;
            const float sx = ((const float*)(sm + SM_SXS))[ty * 4 + p];
            float q1 = a1 * sx, q2 = a2 * sx, q3 = a3 * sx;
            const float M = fmaxf(af, q1);
            int idx = jf;
            if (q1 <= af - TH) {
                // fp32 winner certain
            } else if (q3 >= M - TH) {
                unsigned q = atomicAdd(&g_r2n[h], 1u);
                if (q < R2CAP) { g_r2[h][q] = t; g_best[pair] = 0ULL; }
            } else if (af <= q1 - TH && q2 < M - TH) {
                idx = j1;
            } else {
                unsigned has2 = (q2 >= M - TH) ? 1u : 0u;
                unsigned qq = atomicAdd(&g_r1n, 1u);
                g_r1[qq] = make_uint2((unsigned)pair,
                                      (unsigned)jf | ((unsigned)j1 << 10) |
                                      ((unsigned)j2 << 20) | (has2 << 30));
            }
            idxs[ty * 4 + p] = idx;
        }
    }
    __syncthreads();

    // ---- fused gather: out[t, h*128:+128] = cb[h, idx[t], :] ----
    {
        const float4* cb4 = (const float4*)cb;
        float4* out4 = (float4*)out;
        for (int q = tid; q < TM * (KD / 4); q += NTHR) {
            int t = q >> 5, j = q & 31;
            out4[(size_t)(t0 + t) * (EDIM / 4) + h * (KD / 4) + j] =
                cb4[((size_t)h * OD + idxs[t]) * (KD / 4) + j];
        }
    }
}

// ---------------- tier-1 rescue: exact compare + direct row write ----------------
__global__ __launch_bounds__(256) void rescue1_kernel(const float* __restrict__ x,
                                                      const float* __restrict__ w,
                                                      const float* __restrict__ cb,
                                                      float* __restrict__ out) {
    const unsigned cnt = g_r1n;
    const int l = threadIdx.x & 31;
    const int gw = (blockIdx.x * 256 + threadIdx.x) >> 5;
    for (unsigned e = gw; e < cnt; e += 2048) {
        uint2 ent = g_r1[e];
        int pair = (int)ent.x, t = pair >> 4, h = pair & 15;
        int c0 = (int)(ent.y & 0x3FF);
        int c1 = (int)((ent.y >> 10) & 0x3FF);
        int c2 = (int)((ent.y >> 20) & 0x3FF);
        bool has2 = ((ent.y >> 30) & 1) != 0;
        float4 xv = ((const float4*)(x + (size_t)t * EDIM + h * KD))[l];
        float4 w0 = ((const float4*)(w + ((size_t)h * OD + c0) * KD))[l];
        float4 w1 = ((const float4*)(w + ((size_t)h * OD + c1) * KD))[l];
        float4 w2 = ((const float4*)(w + ((size_t)h * OD + c2) * KD))[l];
        float d0 = xv.x * w0.x + xv.y * w0.y + xv.z * w0.z + xv.w * w0.w;
        float d1 = xv.x * w1.x + xv.y * w1.y + xv.z * w1.z + xv.w * w1.w;
        float d2 = xv.x * w2.x + xv.y * w2.y + xv.z * w2.z + xv.w * w2.w;
#pragma unroll
        for (int off = 16; off; off >>= 1) {
            d0 += __shfl_xor_sync(0xffffffffu, d0, off);
            d1 += __shfl_xor_sync(0xffffffffu, d1, off);
            d2 += __shfl_xor_sync(0xffffffffu, d2, off);
        }
        float bd = d0; int bi = c0;
        if (d1 > bd || (d1 == bd && c1 < bi)) { bd = d1; bi = c1; }
        if (has2 && (d2 > bd || (d2 == bd && c2 < bi))) { bd = d2; bi = c2; }
        ((float4*)out)[(size_t)t * (EDIM / 4) + h * (KD / 4) + l] =
            ((const float4*)cb)[((size_t)h * OD + bi) * (KD / 4) + l];
    }
}

// ---------------- tier-2 rescue: slab-parallel (grid z), early return ----------------
__global__ __launch_bounds__(256) void rescue2_kernel(const float* __restrict__ x) {
    __shared__ __align__(16) float xs[128][36];
    __shared__ int toks[32];
    const int h = blockIdx.x, c = blockIdx.y, slab = blockIdx.z;
    unsigned n = g_r2n[h]; if (n > R2CAP) n = R2CAP;
    const int e0 = slab * 32;
    if (e0 >= (int)n) return;
    const int cnt = ((int)n - e0 < 32) ? ((int)n - e0) : 32;
    const int tid = threadIdx.x;

    if (tid < cnt) toks[tid] = g_r2[h][e0 + tid];
    __syncthreads();
    for (int i = tid; i < cnt * 32; i += 256) {
        int e = i >> 5, k4 = i & 31;
        float4 v = ((const float4*)(x + (size_t)toks[e] * EDIM + h * KD))[k4];
        xs[k4*4+0][e] = v.x; xs[k4*4+1][e] = v.y;
        xs[k4*4+2][e] = v.z; xs[k4*4+3][e] = v.w;
    }
    __syncthreads();

    const int ol = tid & 127, tg = tid >> 7;
    const int o = c * 128 + ol;
    const float* wcol = g_wt + (size_t)h * KD * OD + o;

    float acc[16];
#pragma unroll
    for (int u = 0; u < 16; u++) acc[u] = 0.f;

#pragma unroll 4
    for (int k = 0; k < KD; k++) {
        float wv = wcol[(size_t)k * OD];
        float4 x0 = *(const float4*)&xs[k][tg * 16];
        float4 x1 = *(const float4*)&xs[k][tg * 16 + 4];
        float4 x2 = *(const float4*)&xs[k][tg * 16 + 8];
        float4 x3 = *(const float4*)&xs[k][tg * 16 + 12];
        acc[0]  += wv * x0.x; acc[1]  += wv * x0.y; acc[2]  += wv * x0.z; acc[3]  += wv * x0.w;
        acc[4]  += wv * x1.x; acc[5]  += wv * x1.y; acc[6]  += wv * x1.z; acc[7]  += wv * x1.w;
        acc[8]  += wv * x2.x; acc[9]  += wv * x2.y; acc[10] += wv * x2.z; acc[11] += wv * x2.w;
        acc[12] += wv * x3.x; acc[13] += wv * x3.y; acc[14] += wv * x3.z; acc[15] += wv * x3.w;
    }

#pragma unroll
    for (int u = 0; u < 16; u++) {
        float v = acc[u]; int oo = o;
#pragma unroll
        for (int off = 16; off; off >>= 1) {
            float v2 = __shfl_xor_sync(0xffffffffu, v, off);
            int   o2 = __shfl_xor_sync(0xffffffffu, oo, off);
            if (v2 > v || (v2 == v && o2 < oo)) { v = v2; oo = o2; }
        }
        int te = tg * 16 + u;
        if ((tid & 31) == 0 && te < cnt) {
            u64 key = ((u64)enc_f(v) << 32) | (unsigned)(OD - 1 - oo);
            atomicMax(&g_best[toks[te] * NHEADS + h], key);
        }
    }
}

// decode tier-2 winners and write output rows directly
__global__ void decode_kernel(const float* __restrict__ cb, float* __restrict__ out) {
    const int h = blockIdx.x;
    unsigned n = g_r2n[h]; if (n > R2CAP) n = R2CAP;
    const int wid = threadIdx.x >> 5, l = threadIdx.x & 31;
    for (unsigned e = wid; e < n; e += 8) {
        int t = g_r2[h][e];
        u64 key = g_best[t * NHEADS + h];
        int bi = (OD - 1) - (int)(key & 0xFFFFFFFFULL);
        ((float4*)out)[(size_t)t * (EDIM / 4) + h * (KD / 4) + l] =
            ((const float4*)cb)[((size_t)h * OD + bi) * (KD / 4) + l];
    }
}

extern "C" void kernel_launch(void* const* d_in, const int* in_sizes, int n_in,
                              void* d_out, int out_size) {
    const float* x  = (const float*)d_in[0];
    const float* w  = (const float*)d_in[1];
    const float* cb = (const float*)d_in[2];
    // d_in[3] temperature: mathematically irrelevant in the forward pass.
    float* out = (float*)d_out;

    cudaFuncSetAttribute(vq_hybrid_kernel,
                         cudaFuncAttributeMaxDynamicSharedMemorySize, SM_TOT);

    prep_w_kernel<<<dim3(OD / 32, NHEADS), 256>>>(w);
    vq_hybrid_kernel<<<dim3(NTOK / TM, NHEADS), NTHR, SM_TOT>>>(x, cb, out);
    rescue1_kernel<<<256, 256>>>(x, w, cb, out);
    rescue2_kernel<<<dim3(NHEADS, 8, R2CAP / 32), 256>>>(x);
    decode_kernel<<<NHEADS, 256>>>(cb, out);
}